// round 12
// baseline (speedup 1.0000x reference)
#include <cuda_runtime.h>
#include <cuda_fp16.h>
#include <cstdint>

// GRUController via fp16 tensor cores (mma.sync m16n8k16, fp32 accum/state).
// R12: 512 threads = 16 warps = 2 row-groups x 8 col-groups (one n8 tile/warp).
// L1 B-fragments in registers; L0 B-fragments from smem (reg budget).

typedef uint32_t u32;

#define TIN  512
#define TOUT 180
#define NT   512
#define HSW  40   // h row stride in 32-bit words

// 32-bit-word offsets in dynamic smem
#define OFF_BL0   0        // 96 frags * 64 words  (L0 B-frags, resident)
#define OFF_BL1   6144     // 192 frags * 64 words (staging for L1 B-frags)
#define OFF_H0A   18432    // 64*40 words
#define OFF_H0B   20992
#define OFF_H1A   23552
#define OFF_H1B   26112
#define OFF_B0    28672    // 256 floats: bR,bZ,bI,bH
#define OFF_B1    28928
#define OFF_W0S   29184    // 384 floats: layer0 input weights [j][2]
#define OFF_XST   29568    // 2 slots * 64 rows * 2 floats
#define OFF_OUTW  29824    // 64
#define OFF_PART  29888    // 8 jg * 64 rows
#define SMEM_FLOATS 30400
#define SMEM_BYTES  (SMEM_FLOATS * 4)   // 121,600 B

__device__ __forceinline__ float tanh_t(float x) {
    float y; asm("tanh.approx.f32 %0,%1;" : "=f"(y) : "f"(x)); return y;
}
__device__ __forceinline__ float sigm_t(float x) {
    return fmaf(tanh_t(0.5f * x), 0.5f, 0.5f);
}
__device__ __forceinline__ u32 pack_h2(float lo, float hi) {
    __half2 h = __floats2half2_rn(lo, hi);
    return *(u32*)&h;
}
__device__ __forceinline__ float2 unpack_h2(u32 v) {
    return __half22float2(*(__half2*)&v);
}
__device__ __forceinline__ void mma16(float* c, u32 a0, u32 a1, u32 a2, u32 a3,
                                      u32 b0, u32 b1) {
    asm volatile(
        "mma.sync.aligned.m16n8k16.row.col.f32.f16.f16.f32 "
        "{%0,%1,%2,%3},{%4,%5,%6,%7},{%8,%9},{%0,%1,%2,%3};"
        : "+f"(c[0]), "+f"(c[1]), "+f"(c[2]), "+f"(c[3])
        : "r"(a0), "r"(a1), "r"(a2), "r"(a3), "r"(b0), "r"(b1));
}

// B-frag staging (fp16) into smem: frag n8 x k16. lane l: word0 = W[n][k0..k0+1],
// word1 = W[n][k0+8..k0+9], n = base + (l>>2), k0 = chunk*16 + (l&3)*2.
__device__ void load_weights_tc(float* __restrict__ sm,
                                const float* __restrict__ Wih0, int nin,
                                const float* __restrict__ Whh0,
                                const float* __restrict__ bih0, const float* __restrict__ bhh0,
                                const float* __restrict__ Wih1, const float* __restrict__ Whh1,
                                const float* __restrict__ bih1, const float* __restrict__ bhh1,
                                int tid) {
    u32* smw = (u32*)sm;
    for (int i = tid; i < 96 * 32; i += NT) {
        int f = i >> 5, l = i & 31;
        int gate = f >> 5, rem = f & 31, nt = rem >> 2, ch = rem & 3;
        int row = gate * 64 + nt * 8 + (l >> 2);
        int k0 = ch * 16 + (l & 3) * 2;
        smw[OFF_BL0 + f * 64 + l * 2]     = pack_h2(Whh0[row * 64 + k0],     Whh0[row * 64 + k0 + 1]);
        smw[OFF_BL0 + f * 64 + l * 2 + 1] = pack_h2(Whh0[row * 64 + k0 + 8], Whh0[row * 64 + k0 + 9]);
    }
    for (int i = tid; i < 192 * 32; i += NT) {
        int f = i >> 5, l = i & 31;
        int gate = f >> 6, rem = f & 63, nt = rem >> 3, ch = rem & 7;
        int row = gate * 64 + nt * 8 + (l >> 2);
        int k0 = (ch & 3) * 16 + (l & 3) * 2;
        const float* src = (ch < 4) ? Wih1 : Whh1;
        smw[OFF_BL1 + f * 64 + l * 2]     = pack_h2(src[row * 64 + k0],     src[row * 64 + k0 + 1]);
        smw[OFF_BL1 + f * 64 + l * 2 + 1] = pack_h2(src[row * 64 + k0 + 8], src[row * 64 + k0 + 9]);
    }
    for (int j = tid; j < 192; j += NT) {
        sm[OFF_W0S + j * 2]     = Wih0[j * nin];
        sm[OFF_W0S + j * 2 + 1] = (nin == 2) ? Wih0[j * 2 + 1] : 0.0f;
    }
    if (tid < 64) {
        sm[OFF_B0 + tid]       = bih0[tid]       + bhh0[tid];
        sm[OFF_B0 + 64 + tid]  = bih0[64 + tid]  + bhh0[64 + tid];
        sm[OFF_B0 + 128 + tid] = bih0[128 + tid];
        sm[OFF_B0 + 192 + tid] = bhh0[128 + tid];
        sm[OFF_B1 + tid]       = bih1[tid]       + bhh1[tid];
        sm[OFF_B1 + 64 + tid]  = bih1[64 + tid]  + bhh1[64 + tid];
        sm[OFF_B1 + 128 + tid] = bih1[128 + tid];
        sm[OFF_B1 + 192 + tid] = bhh1[128 + tid];
    }
}

extern "C" __global__ void __launch_bounds__(NT, 1)
gru_controller_kernel(const float* __restrict__ x,
                      const float* eWih0, const float* eWhh0, const float* ebih0, const float* ebhh0,
                      const float* eWih1, const float* eWhh1, const float* ebih1, const float* ebhh1,
                      const float* dWih0, const float* dWhh0, const float* dbih0, const float* dbhh0,
                      const float* dWih1, const float* dWhh1, const float* dbih1, const float* dbhh1,
                      const float* __restrict__ outW, const float* __restrict__ outb,
                      float* __restrict__ out) {
    extern __shared__ float sm[];
    u32* smw = (u32*)sm;
    const int tid = threadIdx.x;
    const int w = tid >> 5, l = tid & 31;
    const int mg = w >> 3, jg = w & 7;      // 2 row-groups x 8 col-groups
    const int g = l >> 2, tq = l & 3;
    const int rb0 = mg * 32;
    const int rbase = blockIdx.x * 64;

    float aR[2][4], aZ[2][4], aI[2][4], aH[2][4];   // [mt][q]
    uint2 bl1[3][8];                                 // L1 B-frags in regs

    auto load_b_regs = [&]() {
#pragma unroll
        for (int gate = 0; gate < 3; gate++)
#pragma unroll
            for (int ch = 0; ch < 8; ch++)
                bl1[gate][ch] =
                    *(const uint2*)&smw[OFF_BL1 + (gate * 64 + jg * 8 + ch) * 64 + l * 2];
    };

    auto init_gates = [&](const float* b, bool withX, int slot) {
        const int col0 = jg * 8 + 2 * tq;
        float2 bR = *(const float2*)&b[col0];
        float2 bZ = *(const float2*)&b[64 + col0];
        float2 bI = *(const float2*)&b[128 + col0];
        float2 bH = *(const float2*)&b[192 + col0];
        if (withX) {
            float2 wr0 = *(const float2*)&sm[OFF_W0S + col0 * 2];
            float2 wr1 = *(const float2*)&sm[OFF_W0S + (col0 + 1) * 2];
            float2 wz0 = *(const float2*)&sm[OFF_W0S + (64 + col0) * 2];
            float2 wz1 = *(const float2*)&sm[OFF_W0S + (64 + col0 + 1) * 2];
            float2 wn0 = *(const float2*)&sm[OFF_W0S + (128 + col0) * 2];
            float2 wn1 = *(const float2*)&sm[OFF_W0S + (128 + col0 + 1) * 2];
#pragma unroll
            for (int mt = 0; mt < 2; mt++) {
                float2 xlo = *(const float2*)&sm[OFF_XST + slot * 128 + (rb0 + mt * 16 + g) * 2];
                float2 xhi = *(const float2*)&sm[OFF_XST + slot * 128 + (rb0 + mt * 16 + g + 8) * 2];
#pragma unroll
                for (int h = 0; h < 2; h++) {
                    float x0 = h ? xhi.x : xlo.x;
                    float x1 = h ? xhi.y : xlo.y;
                    aR[mt][2 * h]     = bR.x + x0 * wr0.x + x1 * wr0.y;
                    aR[mt][2 * h + 1] = bR.y + x0 * wr1.x + x1 * wr1.y;
                    aZ[mt][2 * h]     = bZ.x + x0 * wz0.x + x1 * wz0.y;
                    aZ[mt][2 * h + 1] = bZ.y + x0 * wz1.x + x1 * wz1.y;
                    aI[mt][2 * h]     = bI.x + x0 * wn0.x + x1 * wn0.y;
                    aI[mt][2 * h + 1] = bI.y + x0 * wn1.x + x1 * wn1.y;
                    aH[mt][2 * h]     = bH.x;
                    aH[mt][2 * h + 1] = bH.y;
                }
            }
        } else {
#pragma unroll
            for (int mt = 0; mt < 2; mt++) {
                aR[mt][0] = bR.x; aR[mt][1] = bR.y; aR[mt][2] = bR.x; aR[mt][3] = bR.y;
                aZ[mt][0] = bZ.x; aZ[mt][1] = bZ.y; aZ[mt][2] = bZ.x; aZ[mt][3] = bZ.y;
                aI[mt][0] = bI.x; aI[mt][1] = bI.y; aI[mt][2] = bI.x; aI[mt][3] = bI.y;
                aH[mt][0] = bH.x; aH[mt][1] = bH.y; aH[mt][2] = bH.x; aH[mt][3] = bH.y;
            }
        }
    };

    // L0: B-frags read from smem (resident), frag f = gate*32 + jg*4 + ch
    auto mma_l0 = [&](const u32* hs) {
#pragma unroll
        for (int ch = 0; ch < 4; ch++) {
            u32 a[2][4];
#pragma unroll
            for (int mt = 0; mt < 2; mt++) {
                int rlo = rb0 + mt * 16 + g;
                uint2 lo = *(const uint2*)&hs[rlo * HSW + ch * 8 + tq * 2];
                uint2 hi = *(const uint2*)&hs[(rlo + 8) * HSW + ch * 8 + tq * 2];
                a[mt][0] = lo.x; a[mt][1] = hi.x; a[mt][2] = lo.y; a[mt][3] = hi.y;
            }
            uint2 bR = *(const uint2*)&smw[OFF_BL0 + (0 * 32 + jg * 4 + ch) * 64 + l * 2];
            uint2 bZ = *(const uint2*)&smw[OFF_BL0 + (1 * 32 + jg * 4 + ch) * 64 + l * 2];
            uint2 bN = *(const uint2*)&smw[OFF_BL0 + (2 * 32 + jg * 4 + ch) * 64 + l * 2];
#pragma unroll
            for (int mt = 0; mt < 2; mt++) {
                mma16(aR[mt], a[mt][0], a[mt][1], a[mt][2], a[mt][3], bR.x, bR.y);
                mma16(aZ[mt], a[mt][0], a[mt][1], a[mt][2], a[mt][3], bZ.x, bZ.y);
                mma16(aH[mt], a[mt][0], a[mt][1], a[mt][2], a[mt][3], bN.x, bN.y);
            }
        }
    };

    auto mma_l1 = [&](const u32* h0, const u32* h1) {
#pragma unroll
        for (int ch = 0; ch < 8; ch++) {
            const u32* hs = (ch < 4) ? h0 : h1;
            int kw = (ch & 3) * 8 + tq * 2;
            u32 a[2][4];
#pragma unroll
            for (int mt = 0; mt < 2; mt++) {
                int rlo = rb0 + mt * 16 + g;
                uint2 lo = *(const uint2*)&hs[rlo * HSW + kw];
                uint2 hi = *(const uint2*)&hs[(rlo + 8) * HSW + kw];
                a[mt][0] = lo.x; a[mt][1] = hi.x; a[mt][2] = lo.y; a[mt][3] = hi.y;
            }
#pragma unroll
            for (int mt = 0; mt < 2; mt++) {
                mma16(aR[mt], a[mt][0], a[mt][1], a[mt][2], a[mt][3],
                      bl1[0][ch].x, bl1[0][ch].y);
                mma16(aZ[mt], a[mt][0], a[mt][1], a[mt][2], a[mt][3],
                      bl1[1][ch].x, bl1[1][ch].y);
                if (ch < 4)
                    mma16(aI[mt], a[mt][0], a[mt][1], a[mt][2], a[mt][3],
                          bl1[2][ch].x, bl1[2][ch].y);
                else
                    mma16(aH[mt], a[mt][0], a[mt][1], a[mt][2], a[mt][3],
                          bl1[2][ch].x, bl1[2][ch].y);
            }
        }
    };

    // h word for col pair of n-tile jg at 2tq: pair q = 4*jg+tq -> word 8(jg>>1)+2tq+(jg&1)
    auto update = [&](const u32* hs, u32* hd, bool head) {
        const int wq = 8 * (jg >> 1) + 2 * tq + (jg & 1);
        float pr[2][2] = {{0.0f, 0.0f}, {0.0f, 0.0f}};
        float2 wo = head ? *(const float2*)&sm[OFF_OUTW + jg * 8 + 2 * tq]
                         : make_float2(0.f, 0.f);
#pragma unroll
        for (int mt = 0; mt < 2; mt++) {
            int rlo = rb0 + mt * 16 + g, rhi = rlo + 8;
            float2 hlo = unpack_h2(hs[rlo * HSW + wq]);
            float2 hhi = unpack_h2(hs[rhi * HSW + wq]);
            const float hold[4] = {hlo.x, hlo.y, hhi.x, hhi.y};
            float o[4];
#pragma unroll
            for (int q = 0; q < 4; q++) {
                float r = sigm_t(aR[mt][q]);
                float z = sigm_t(aZ[mt][q]);
                float n = tanh_t(fmaf(r, aH[mt][q], aI[mt][q]));
                o[q] = fmaf(z, hold[q] - n, n);
            }
            hd[rlo * HSW + wq] = pack_h2(o[0], o[1]);
            hd[rhi * HSW + wq] = pack_h2(o[2], o[3]);
            if (head) {
                pr[mt][0] = fmaf(o[0], wo.x, fmaf(o[1], wo.y, pr[mt][0]));
                pr[mt][1] = fmaf(o[2], wo.x, fmaf(o[3], wo.y, pr[mt][1]));
            }
        }
        if (head) {
#pragma unroll
            for (int mt = 0; mt < 2; mt++)
#pragma unroll
                for (int h = 0; h < 2; h++) {
                    float v = pr[mt][h];
                    v += __shfl_xor_sync(0xffffffffu, v, 1);
                    v += __shfl_xor_sync(0xffffffffu, v, 2);
                    if (tq == 0)
                        sm[OFF_PART + jg * 64 + rb0 + mt * 16 + h * 8 + g] = v;
                }
        }
    };

    // ---------------- setup ----------------
    for (int i = tid; i < 4 * 64 * HSW; i += NT) smw[OFF_H0A + i] = 0u;
    load_weights_tc(sm, eWih0, 2, eWhh0, ebih0, ebhh0, eWih1, eWhh1, ebih1, ebhh1, tid);
    if (tid < 64) sm[OFF_OUTW + tid] = outW[tid];
    if (tid < 128) {
        int r = tid >> 1, ch = tid & 1;
        sm[OFF_XST + r * 2 + ch] = x[((long)(rbase + r) * TIN) * 2 + ch];
    }
    __syncthreads();
    load_b_regs();

    int p = 0;
    // ================= encoder (1 barrier/step) =================
    for (int t = 0; t < TIN; t++) {
        const u32* h0s = smw + (p ? OFF_H0B : OFF_H0A);
        u32*       h0d = smw + (p ? OFF_H0A : OFF_H0B);
        const u32* h1s = smw + (p ? OFF_H1B : OFF_H1A);
        u32*       h1d = smw + (p ? OFF_H1A : OFF_H1B);

        if (t + 1 < TIN && tid < 128) {
            int r = tid >> 1, ch = tid & 1;
            sm[OFF_XST + ((t + 1) & 1) * 128 + r * 2 + ch] =
                x[((long)(rbase + r) * TIN + (t + 1)) * 2 + ch];
        }

        init_gates(sm + OFF_B0, true, t & 1);
        mma_l0(h0s);
        update(h0s, h0d, false);
        __syncthreads();   // layer0-write -> layer1-read

        init_gates(sm + OFF_B1, false, 0);
        mma_l1(h0d, h1s);
        update(h1s, h1d, false);
        p ^= 1;
    }

    // ================= swap to decoder weights =================
    __syncthreads();
    load_weights_tc(sm, dWih0, 1, dWhh0, dbih0, dbhh0, dWih1, dWhh1, dbih1, dbhh1, tid);
    if (tid < 64) {
        sm[OFF_XST + tid * 2]     = 0.0f;
        sm[OFF_XST + tid * 2 + 1] = 0.0f;
    }
    __syncthreads();
    load_b_regs();
    const float ob = outb[0];

    // ================= decoder =================
    for (int t = 0; t < TOUT; t++) {
        const u32* h0s = smw + (p ? OFF_H0B : OFF_H0A);
        u32*       h0d = smw + (p ? OFF_H0A : OFF_H0B);
        const u32* h1s = smw + (p ? OFF_H1B : OFF_H1A);
        u32*       h1d = smw + (p ? OFF_H1A : OFF_H1B);

        init_gates(sm + OFF_B0, true, 0);   // prev in slot 0
        mma_l0(h0s);
        update(h0s, h0d, false);
        __syncthreads();

        init_gates(sm + OFF_B1, false, 0);
        mma_l1(h0d, h1s);
        update(h1s, h1d, true);
        __syncthreads();

        if (tid < 64) {
            float acc = ob;
#pragma unroll
            for (int c = 0; c < 8; c++) acc += sm[OFF_PART + c * 64 + tid];
            sm[OFF_XST + tid * 2] = acc;     // prev for next step
            out[(long)(rbase + tid) * TOUT + t] = acc;
        }
        __syncthreads();
        p ^= 1;
    }
}

extern "C" void kernel_launch(void* const* d_in, const int* in_sizes, int n_in,
                              void* d_out, int out_size) {
    const float* x     = (const float*)d_in[0];
    const float* eWih0 = (const float*)d_in[1];
    const float* eWhh0 = (const float*)d_in[2];
    const float* ebih0 = (const float*)d_in[3];
    const float* ebhh0 = (const float*)d_in[4];
    const float* eWih1 = (const float*)d_in[5];
    const float* eWhh1 = (const float*)d_in[6];
    const float* ebih1 = (const float*)d_in[7];
    const float* ebhh1 = (const float*)d_in[8];
    const float* dWih0 = (const float*)d_in[9];
    const float* dWhh0 = (const float*)d_in[10];
    const float* dbih0 = (const float*)d_in[11];
    const float* dbhh0 = (const float*)d_in[12];
    const float* dWih1 = (const float*)d_in[13];
    const float* dWhh1 = (const float*)d_in[14];
    const float* dbih1 = (const float*)d_in[15];
    const float* dbhh1 = (const float*)d_in[16];
    const float* outW  = (const float*)d_in[17];
    const float* outb  = (const float*)d_in[18];
    float* out = (float*)d_out;

    cudaFuncSetAttribute(gru_controller_kernel,
                         cudaFuncAttributeMaxDynamicSharedMemorySize, SMEM_BYTES);
    gru_controller_kernel<<<128, NT, SMEM_BYTES>>>(
        x, eWih0, eWhh0, ebih0, ebhh0, eWih1, eWhh1, ebih1, ebhh1,
        dWih0, dWhh0, dbih0, dbhh0, dWih1, dWhh1, dbih1, dbhh1,
        outW, outb, out);
}

// round 14
// speedup vs baseline: 1.1368x; 1.1368x over previous
#include <cuda_runtime.h>
#include <cuda_fp16.h>
#include <cstdint>

// GRUController via fp16 tensor cores (mma.sync m16n8k16, fp32 accum/epilogue).
// R14: R11 arithmetic (fp32 epilogue, B-frags in registers) + independent
// 128-thread halves synchronized with named barriers.
// 128 CTAs x 64 rows, 256 threads = 2 halves x 4 col-group warps.

typedef uint32_t u32;

#define TIN  512
#define TOUT 180
#define NT   256
#define HSW  40   // h row stride in 32-bit words

// 32-bit-word offsets in dynamic smem
#define OFF_BL0   0        // 96 frags * 64 words  (staging for L0 B-frags)
#define OFF_BL1   6144     // 192 frags * 64 words (staging for L1 B-frags)
#define OFF_H0A   18432    // 64*40 words
#define OFF_H0B   20992
#define OFF_H1A   23552
#define OFF_H1B   26112
#define OFF_B0    28672    // 256 floats: bR,bZ,bI,bH
#define OFF_B1    28928
#define OFF_W0S   29184    // 384 floats: layer0 input weights [j][2]
#define OFF_XST   29568    // 2 slots * 64 rows * 2 floats
#define OFF_OUTW  29824    // 64
#define OFF_PART  29888    // 4 jg * 64 rows
#define SMEM_FLOATS 30208
#define SMEM_BYTES  (SMEM_FLOATS * 4)   // 120,832 B

__device__ __forceinline__ float tanh_t(float x) {
    float y; asm("tanh.approx.f32 %0,%1;" : "=f"(y) : "f"(x)); return y;
}
__device__ __forceinline__ float sigm_t(float x) {
    return fmaf(tanh_t(0.5f * x), 0.5f, 0.5f);
}
__device__ __forceinline__ u32 pack_h2(float lo, float hi) {
    __half2 h = __floats2half2_rn(lo, hi);
    return *(u32*)&h;
}
__device__ __forceinline__ float2 unpack_h2(u32 v) {
    return __half22float2(*(__half2*)&v);
}
__device__ __forceinline__ void mma16(float* c, u32 a0, u32 a1, u32 a2, u32 a3,
                                      u32 b0, u32 b1) {
    asm volatile(
        "mma.sync.aligned.m16n8k16.row.col.f32.f16.f16.f32 "
        "{%0,%1,%2,%3},{%4,%5,%6,%7},{%8,%9},{%0,%1,%2,%3};"
        : "+f"(c[0]), "+f"(c[1]), "+f"(c[2]), "+f"(c[3])
        : "r"(a0), "r"(a1), "r"(a2), "r"(a3), "r"(b0), "r"(b1));
}

// B-frag staging (fp16) into smem: frag n8 x k16. lane l: word0 = W[n][k0..k0+1],
// word1 = W[n][k0+8..k0+9], n = base + (l>>2), k0 = chunk*16 + (l&3)*2.
__device__ void load_weights_tc(float* __restrict__ sm,
                                const float* __restrict__ Wih0, int nin,
                                const float* __restrict__ Whh0,
                                const float* __restrict__ bih0, const float* __restrict__ bhh0,
                                const float* __restrict__ Wih1, const float* __restrict__ Whh1,
                                const float* __restrict__ bih1, const float* __restrict__ bhh1,
                                int tid) {
    u32* smw = (u32*)sm;
    for (int i = tid; i < 96 * 32; i += NT) {
        int f = i >> 5, l = i & 31;
        int gate = f >> 5, rem = f & 31, nt = rem >> 2, ch = rem & 3;
        int row = gate * 64 + nt * 8 + (l >> 2);
        int k0 = ch * 16 + (l & 3) * 2;
        smw[OFF_BL0 + f * 64 + l * 2]     = pack_h2(Whh0[row * 64 + k0],     Whh0[row * 64 + k0 + 1]);
        smw[OFF_BL0 + f * 64 + l * 2 + 1] = pack_h2(Whh0[row * 64 + k0 + 8], Whh0[row * 64 + k0 + 9]);
    }
    for (int i = tid; i < 192 * 32; i += NT) {
        int f = i >> 5, l = i & 31;
        int gate = f >> 6, rem = f & 63, nt = rem >> 3, ch = rem & 7;
        int row = gate * 64 + nt * 8 + (l >> 2);
        int k0 = (ch & 3) * 16 + (l & 3) * 2;
        const float* src = (ch < 4) ? Wih1 : Whh1;
        smw[OFF_BL1 + f * 64 + l * 2]     = pack_h2(src[row * 64 + k0],     src[row * 64 + k0 + 1]);
        smw[OFF_BL1 + f * 64 + l * 2 + 1] = pack_h2(src[row * 64 + k0 + 8], src[row * 64 + k0 + 9]);
    }
    for (int j = tid; j < 192; j += NT) {
        sm[OFF_W0S + j * 2]     = Wih0[j * nin];
        sm[OFF_W0S + j * 2 + 1] = (nin == 2) ? Wih0[j * 2 + 1] : 0.0f;
    }
    if (tid < 64) {
        sm[OFF_B0 + tid]       = bih0[tid]       + bhh0[tid];
        sm[OFF_B0 + 64 + tid]  = bih0[64 + tid]  + bhh0[64 + tid];
        sm[OFF_B0 + 128 + tid] = bih0[128 + tid];
        sm[OFF_B0 + 192 + tid] = bhh0[128 + tid];
        sm[OFF_B1 + tid]       = bih1[tid]       + bhh1[tid];
        sm[OFF_B1 + 64 + tid]  = bih1[64 + tid]  + bhh1[64 + tid];
        sm[OFF_B1 + 128 + tid] = bih1[128 + tid];
        sm[OFF_B1 + 192 + tid] = bhh1[128 + tid];
    }
}

extern "C" __global__ void __launch_bounds__(NT, 1)
gru_controller_kernel(const float* __restrict__ x,
                      const float* eWih0, const float* eWhh0, const float* ebih0, const float* ebhh0,
                      const float* eWih1, const float* eWhh1, const float* ebih1, const float* ebhh1,
                      const float* dWih0, const float* dWhh0, const float* dbih0, const float* dbhh0,
                      const float* dWih1, const float* dWhh1, const float* dbih1, const float* dbhh1,
                      const float* __restrict__ outW, const float* __restrict__ outb,
                      float* __restrict__ out) {
    extern __shared__ float sm[];
    u32* smw = (u32*)sm;
    const int tid = threadIdx.x;
    const int w = tid >> 5, l = tid & 31;
    const int mg = w >> 2, jg = w & 3;      // half mg (rows mg*32..+31), col-group jg
    const int g = l >> 2, tq = l & 3;
    const int rb0 = mg * 32;
    const int rbase = blockIdx.x * 64;
    const int lt = tid & 127;               // thread id within half

    // half-scoped barrier (128 threads of this half)
    auto barh = [&]() {
        asm volatile("bar.sync %0, 128;" :: "r"(1 + mg) : "memory");
    };

    float aR[2][2][4], aZ[2][2][4], aI[2][2][4], aH[2][2][4];   // [mt][ntl][q]
    uint2 bl0[3][4][2];   // register-resident B fragments [gate][ch][ntl]
    uint2 bl1[3][8][2];

    auto load_b_regs = [&]() {
#pragma unroll
        for (int gate = 0; gate < 3; gate++)
#pragma unroll
            for (int ch = 0; ch < 4; ch++)
#pragma unroll
                for (int ntl = 0; ntl < 2; ntl++) {
                    int nt = jg * 2 + ntl;
                    bl0[gate][ch][ntl] =
                        *(const uint2*)&smw[OFF_BL0 + (gate * 32 + nt * 4 + ch) * 64 + l * 2];
                }
#pragma unroll
        for (int gate = 0; gate < 3; gate++)
#pragma unroll
            for (int ch = 0; ch < 8; ch++)
#pragma unroll
                for (int ntl = 0; ntl < 2; ntl++) {
                    int nt = jg * 2 + ntl;
                    bl1[gate][ch][ntl] =
                        *(const uint2*)&smw[OFF_BL1 + (gate * 64 + nt * 8 + ch) * 64 + l * 2];
                }
    };

    auto init_gates = [&](const float* b, bool withX, int slot) {
        float2 xv[2][2];
        if (withX) {
#pragma unroll
            for (int mt = 0; mt < 2; mt++) {
                xv[mt][0] = *(const float2*)&sm[OFF_XST + slot * 128 + (rb0 + mt * 16 + g) * 2];
                xv[mt][1] = *(const float2*)&sm[OFF_XST + slot * 128 + (rb0 + mt * 16 + g + 8) * 2];
            }
        }
#pragma unroll
        for (int ntl = 0; ntl < 2; ntl++) {
            int col0 = (jg * 2 + ntl) * 8 + 2 * tq;
            float2 bR = *(const float2*)&b[col0];
            float2 bZ = *(const float2*)&b[64 + col0];
            float2 bI = *(const float2*)&b[128 + col0];
            float2 bH = *(const float2*)&b[192 + col0];
            if (withX) {
                float2 wr0 = *(const float2*)&sm[OFF_W0S + col0 * 2];
                float2 wr1 = *(const float2*)&sm[OFF_W0S + (col0 + 1) * 2];
                float2 wz0 = *(const float2*)&sm[OFF_W0S + (64 + col0) * 2];
                float2 wz1 = *(const float2*)&sm[OFF_W0S + (64 + col0 + 1) * 2];
                float2 wn0 = *(const float2*)&sm[OFF_W0S + (128 + col0) * 2];
                float2 wn1 = *(const float2*)&sm[OFF_W0S + (128 + col0 + 1) * 2];
#pragma unroll
                for (int mt = 0; mt < 2; mt++) {
#pragma unroll
                    for (int h = 0; h < 2; h++) {
                        float x0 = xv[mt][h].x, x1 = xv[mt][h].y;
                        aR[mt][ntl][2 * h]     = bR.x + x0 * wr0.x + x1 * wr0.y;
                        aR[mt][ntl][2 * h + 1] = bR.y + x0 * wr1.x + x1 * wr1.y;
                        aZ[mt][ntl][2 * h]     = bZ.x + x0 * wz0.x + x1 * wz0.y;
                        aZ[mt][ntl][2 * h + 1] = bZ.y + x0 * wz1.x + x1 * wz1.y;
                        aI[mt][ntl][2 * h]     = bI.x + x0 * wn0.x + x1 * wn0.y;
                        aI[mt][ntl][2 * h + 1] = bI.y + x0 * wn1.x + x1 * wn1.y;
                        aH[mt][ntl][2 * h]     = bH.x;
                        aH[mt][ntl][2 * h + 1] = bH.y;
                    }
                }
            } else {
#pragma unroll
                for (int mt = 0; mt < 2; mt++) {
                    aR[mt][ntl][0] = bR.x; aR[mt][ntl][1] = bR.y; aR[mt][ntl][2] = bR.x; aR[mt][ntl][3] = bR.y;
                    aZ[mt][ntl][0] = bZ.x; aZ[mt][ntl][1] = bZ.y; aZ[mt][ntl][2] = bZ.x; aZ[mt][ntl][3] = bZ.y;
                    aI[mt][ntl][0] = bI.x; aI[mt][ntl][1] = bI.y; aI[mt][ntl][2] = bI.x; aI[mt][ntl][3] = bI.y;
                    aH[mt][ntl][0] = bH.x; aH[mt][ntl][1] = bH.y; aH[mt][ntl][2] = bH.x; aH[mt][ntl][3] = bH.y;
                }
            }
        }
    };

    auto mma_l0 = [&](const u32* hs) {
#pragma unroll
        for (int ch = 0; ch < 4; ch++) {
            u32 a[2][4];
#pragma unroll
            for (int mt = 0; mt < 2; mt++) {
                int rlo = rb0 + mt * 16 + g;
                uint2 lo = *(const uint2*)&hs[rlo * HSW + ch * 8 + tq * 2];
                uint2 hi = *(const uint2*)&hs[(rlo + 8) * HSW + ch * 8 + tq * 2];
                a[mt][0] = lo.x; a[mt][1] = hi.x; a[mt][2] = lo.y; a[mt][3] = hi.y;
            }
#pragma unroll
            for (int ntl = 0; ntl < 2; ntl++)
#pragma unroll
                for (int mt = 0; mt < 2; mt++) {
                    mma16(aR[mt][ntl], a[mt][0], a[mt][1], a[mt][2], a[mt][3],
                          bl0[0][ch][ntl].x, bl0[0][ch][ntl].y);
                    mma16(aZ[mt][ntl], a[mt][0], a[mt][1], a[mt][2], a[mt][3],
                          bl0[1][ch][ntl].x, bl0[1][ch][ntl].y);
                    mma16(aH[mt][ntl], a[mt][0], a[mt][1], a[mt][2], a[mt][3],
                          bl0[2][ch][ntl].x, bl0[2][ch][ntl].y);
                }
        }
    };

    auto mma_l1 = [&](const u32* h0, const u32* h1) {
#pragma unroll
        for (int ch = 0; ch < 8; ch++) {
            const u32* hs = (ch < 4) ? h0 : h1;
            int kw = (ch & 3) * 8 + tq * 2;
            u32 a[2][4];
#pragma unroll
            for (int mt = 0; mt < 2; mt++) {
                int rlo = rb0 + mt * 16 + g;
                uint2 lo = *(const uint2*)&hs[rlo * HSW + kw];
                uint2 hi = *(const uint2*)&hs[(rlo + 8) * HSW + kw];
                a[mt][0] = lo.x; a[mt][1] = hi.x; a[mt][2] = lo.y; a[mt][3] = hi.y;
            }
#pragma unroll
            for (int ntl = 0; ntl < 2; ntl++)
#pragma unroll
                for (int mt = 0; mt < 2; mt++) {
                    mma16(aR[mt][ntl], a[mt][0], a[mt][1], a[mt][2], a[mt][3],
                          bl1[0][ch][ntl].x, bl1[0][ch][ntl].y);
                    mma16(aZ[mt][ntl], a[mt][0], a[mt][1], a[mt][2], a[mt][3],
                          bl1[1][ch][ntl].x, bl1[1][ch][ntl].y);
                    if (ch < 4)
                        mma16(aI[mt][ntl], a[mt][0], a[mt][1], a[mt][2], a[mt][3],
                              bl1[2][ch][ntl].x, bl1[2][ch][ntl].y);
                    else
                        mma16(aH[mt][ntl], a[mt][0], a[mt][1], a[mt][2], a[mt][3],
                              bl1[2][ch][ntl].x, bl1[2][ch][ntl].y);
                }
        }
    };

    // fp32 epilogue (identical to R11). h word for n-tile m at 2tq:
    // pair q = 4m+tq -> word 8(m>>1)+2tq+(m&1)
    auto update = [&](const u32* hs, u32* hd, bool head) {
        float pr[2][2] = {{0.0f, 0.0f}, {0.0f, 0.0f}};
#pragma unroll
        for (int mt = 0; mt < 2; mt++)
#pragma unroll
            for (int ntl = 0; ntl < 2; ntl++) {
                int m = jg * 2 + ntl;
                int wq = 8 * (m >> 1) + 2 * tq + (m & 1);
                int rlo = rb0 + mt * 16 + g, rhi = rlo + 8;
                float2 hlo = unpack_h2(hs[rlo * HSW + wq]);
                float2 hhi = unpack_h2(hs[rhi * HSW + wq]);
                float2 wo = head ? *(const float2*)&sm[OFF_OUTW + m * 8 + 2 * tq]
                                 : make_float2(0.f, 0.f);
                const float hold[4] = {hlo.x, hlo.y, hhi.x, hhi.y};
                float o[4];
#pragma unroll
                for (int q = 0; q < 4; q++) {
                    float r = sigm_t(aR[mt][ntl][q]);
                    float z = sigm_t(aZ[mt][ntl][q]);
                    float n = tanh_t(fmaf(r, aH[mt][ntl][q], aI[mt][ntl][q]));
                    o[q] = fmaf(z, hold[q] - n, n);
                }
                hd[rlo * HSW + wq] = pack_h2(o[0], o[1]);
                hd[rhi * HSW + wq] = pack_h2(o[2], o[3]);
                if (head) {
                    pr[mt][0] = fmaf(o[0], wo.x, fmaf(o[1], wo.y, pr[mt][0]));
                    pr[mt][1] = fmaf(o[2], wo.x, fmaf(o[3], wo.y, pr[mt][1]));
                }
            }
        if (head) {
#pragma unroll
            for (int mt = 0; mt < 2; mt++)
#pragma unroll
                for (int h = 0; h < 2; h++) {
                    float v = pr[mt][h];
                    v += __shfl_xor_sync(0xffffffffu, v, 1);
                    v += __shfl_xor_sync(0xffffffffu, v, 2);
                    if (tq == 0)
                        sm[OFF_PART + jg * 64 + rb0 + mt * 16 + h * 8 + g] = v;
                }
        }
    };

    // stage x(t) for this half's 32 rows into slot
    auto stage_x = [&](int t, int slot) {
        if (lt < 64) {
            int r = rb0 + (lt >> 1), ch = lt & 1;
            sm[OFF_XST + slot * 128 + r * 2 + ch] = x[((long)(rbase + r) * TIN + t) * 2 + ch];
        }
    };

    // ---------------- setup ----------------
    for (int i = tid; i < 4 * 64 * HSW; i += NT) smw[OFF_H0A + i] = 0u;
    load_weights_tc(sm, eWih0, 2, eWhh0, ebih0, ebhh0, eWih1, eWhh1, ebih1, ebhh1, tid);
    if (tid < 64) sm[OFF_OUTW + tid] = outW[tid];
    __syncthreads();
    load_b_regs();
    stage_x(0, 0);
    barh();

    int p = 0;
    // ================= encoder (per-half, 1 named barrier/step) =================
    for (int t = 0; t < TIN; t++) {
        const u32* h0s = smw + (p ? OFF_H0B : OFF_H0A);
        u32*       h0d = smw + (p ? OFF_H0A : OFF_H0B);
        const u32* h1s = smw + (p ? OFF_H1B : OFF_H1A);
        u32*       h1d = smw + (p ? OFF_H1A : OFF_H1B);

        if (t + 1 < TIN) stage_x(t + 1, (t + 1) & 1);

        init_gates(sm + OFF_B0, true, t & 1);
        mma_l0(h0s);
        update(h0s, h0d, false);
        barh();   // layer0-write -> layer1-read (within half)

        init_gates(sm + OFF_B1, false, 0);
        mma_l1(h0d, h1s);
        update(h1s, h1d, false);
        p ^= 1;
    }

    // ================= swap to decoder weights =================
    __syncthreads();   // both halves done with encoder weights/biases
    load_weights_tc(sm, dWih0, 1, dWhh0, dbih0, dbhh0, dWih1, dWhh1, dbih1, dbhh1, tid);
    if (tid < 64) {
        sm[OFF_XST + tid * 2]     = 0.0f;
        sm[OFF_XST + tid * 2 + 1] = 0.0f;
    }
    __syncthreads();
    load_b_regs();
    const float ob = outb[0];

    // ================= decoder (per-half) =================
    for (int t = 0; t < TOUT; t++) {
        const u32* h0s = smw + (p ? OFF_H0B : OFF_H0A);
        u32*       h0d = smw + (p ? OFF_H0A : OFF_H0B);
        const u32* h1s = smw + (p ? OFF_H1B : OFF_H1A);
        u32*       h1d = smw + (p ? OFF_H1A : OFF_H1B);

        init_gates(sm + OFF_B0, true, 0);   // prev in slot 0
        mma_l0(h0s);
        update(h0s, h0d, false);
        barh();

        init_gates(sm + OFF_B1, false, 0);
        mma_l1(h0d, h1s);
        update(h1s, h1d, true);
        barh();

        if (lt < 32) {
            int r = rb0 + lt;
            float acc = ob + sm[OFF_PART + r] + sm[OFF_PART + 64 + r]
                           + sm[OFF_PART + 128 + r] + sm[OFF_PART + 192 + r];
            sm[OFF_XST + r * 2] = acc;     // prev for next step (channel 1 stays 0)
            out[(long)(rbase + r) * TOUT + t] = acc;
        }
        barh();
        p ^= 1;
    }
}

extern "C" void kernel_launch(void* const* d_in, const int* in_sizes, int n_in,
                              void* d_out, int out_size) {
    const float* x     = (const float*)d_in[0];
    const float* eWih0 = (const float*)d_in[1];
    const float* eWhh0 = (const float*)d_in[2];
    const float* ebih0 = (const float*)d_in[3];
    const float* ebhh0 = (const float*)d_in[4];
    const float* eWih1 = (const float*)d_in[5];
    const float* eWhh1 = (const float*)d_in[6];
    const float* ebih1 = (const float*)d_in[7];
    const float* ebhh1 = (const float*)d_in[8];
    const float* dWih0 = (const float*)d_in[9];
    const float* dWhh0 = (const float*)d_in[10];
    const float* dbih0 = (const float*)d_in[11];
    const float* dbhh0 = (const float*)d_in[12];
    const float* dWih1 = (const float*)d_in[13];
    const float* dWhh1 = (const float*)d_in[14];
    const float* dbih1 = (const float*)d_in[15];
    const float* dbhh1 = (const float*)d_in[16];
    const float* outW  = (const float*)d_in[17];
    const float* outb  = (const float*)d_in[18];
    float* out = (float*)d_out;

    cudaFuncSetAttribute(gru_controller_kernel,
                         cudaFuncAttributeMaxDynamicSharedMemorySize, SMEM_BYTES);
    gru_controller_kernel<<<128, NT, SMEM_BYTES>>>(
        x, eWih0, eWhh0, ebih0, ebhh0, eWih1, eWhh1, ebih1, ebhh1,
        dWih0, dWhh0, dbih0, dbhh0, dWih1, dWhh1, dbih1, dbhh1,
        outW, outb, out);
}

// round 15
// speedup vs baseline: 1.1651x; 1.0248x over previous
#include <cuda_runtime.h>
#include <cuda_fp16.h>
#include <cstdint>

// GRUController via fp16 tensor cores (mma.sync m16n8k16, fp32 accum/epilogue).
// R15: 512 threads = 2 independent 256-thread halves (named barriers) x 8 col-group
// warps (one n8 tile each, all 3 gates). ALL B-fragments in registers (72/warp).
// 128 CTAs x 64 rows.

typedef uint32_t u32;

#define TIN  512
#define TOUT 180
#define NT   512
#define HSW  40   // h row stride in 32-bit words

// 32-bit-word offsets in dynamic smem
#define OFF_BL0   0        // 96 frags * 64 words  (staging for L0 B-frags)
#define OFF_BL1   6144     // 192 frags * 64 words (staging for L1 B-frags)
#define OFF_H0A   18432    // 64*40 words
#define OFF_H0B   20992
#define OFF_H1A   23552
#define OFF_H1B   26112
#define OFF_B0    28672    // 256 floats: bR,bZ,bI,bH
#define OFF_B1    28928
#define OFF_W0S   29184    // 384 floats: layer0 input weights [j][2]
#define OFF_XST   29568    // 2 slots * 64 rows * 2 floats
#define OFF_OUTW  29824    // 64
#define OFF_PART  29888    // 8 jg * 64 rows
#define SMEM_FLOATS 30400
#define SMEM_BYTES  (SMEM_FLOATS * 4)   // 121,600 B

__device__ __forceinline__ float tanh_t(float x) {
    float y; asm("tanh.approx.f32 %0,%1;" : "=f"(y) : "f"(x)); return y;
}
__device__ __forceinline__ float sigm_t(float x) {
    return fmaf(tanh_t(0.5f * x), 0.5f, 0.5f);
}
__device__ __forceinline__ u32 pack_h2(float lo, float hi) {
    __half2 h = __floats2half2_rn(lo, hi);
    return *(u32*)&h;
}
__device__ __forceinline__ float2 unpack_h2(u32 v) {
    return __half22float2(*(__half2*)&v);
}
__device__ __forceinline__ void mma16(float* c, u32 a0, u32 a1, u32 a2, u32 a3,
                                      u32 b0, u32 b1) {
    asm volatile(
        "mma.sync.aligned.m16n8k16.row.col.f32.f16.f16.f32 "
        "{%0,%1,%2,%3},{%4,%5,%6,%7},{%8,%9},{%0,%1,%2,%3};"
        : "+f"(c[0]), "+f"(c[1]), "+f"(c[2]), "+f"(c[3])
        : "r"(a0), "r"(a1), "r"(a2), "r"(a3), "r"(b0), "r"(b1));
}

// B-frag staging (fp16) into smem: frag n8 x k16. lane l: word0 = W[n][k0..k0+1],
// word1 = W[n][k0+8..k0+9], n = base + (l>>2), k0 = chunk*16 + (l&3)*2.
__device__ void load_weights_tc(float* __restrict__ sm,
                                const float* __restrict__ Wih0, int nin,
                                const float* __restrict__ Whh0,
                                const float* __restrict__ bih0, const float* __restrict__ bhh0,
                                const float* __restrict__ Wih1, const float* __restrict__ Whh1,
                                const float* __restrict__ bih1, const float* __restrict__ bhh1,
                                int tid) {
    u32* smw = (u32*)sm;
    for (int i = tid; i < 96 * 32; i += NT) {
        int f = i >> 5, l = i & 31;
        int gate = f >> 5, rem = f & 31, nt = rem >> 2, ch = rem & 3;
        int row = gate * 64 + nt * 8 + (l >> 2);
        int k0 = ch * 16 + (l & 3) * 2;
        smw[OFF_BL0 + f * 64 + l * 2]     = pack_h2(Whh0[row * 64 + k0],     Whh0[row * 64 + k0 + 1]);
        smw[OFF_BL0 + f * 64 + l * 2 + 1] = pack_h2(Whh0[row * 64 + k0 + 8], Whh0[row * 64 + k0 + 9]);
    }
    for (int i = tid; i < 192 * 32; i += NT) {
        int f = i >> 5, l = i & 31;
        int gate = f >> 6, rem = f & 63, nt = rem >> 3, ch = rem & 7;
        int row = gate * 64 + nt * 8 + (l >> 2);
        int k0 = (ch & 3) * 16 + (l & 3) * 2;
        const float* src = (ch < 4) ? Wih1 : Whh1;
        smw[OFF_BL1 + f * 64 + l * 2]     = pack_h2(src[row * 64 + k0],     src[row * 64 + k0 + 1]);
        smw[OFF_BL1 + f * 64 + l * 2 + 1] = pack_h2(src[row * 64 + k0 + 8], src[row * 64 + k0 + 9]);
    }
    for (int j = tid; j < 192; j += NT) {
        sm[OFF_W0S + j * 2]     = Wih0[j * nin];
        sm[OFF_W0S + j * 2 + 1] = (nin == 2) ? Wih0[j * 2 + 1] : 0.0f;
    }
    if (tid < 64) {
        sm[OFF_B0 + tid]       = bih0[tid]       + bhh0[tid];
        sm[OFF_B0 + 64 + tid]  = bih0[64 + tid]  + bhh0[64 + tid];
        sm[OFF_B0 + 128 + tid] = bih0[128 + tid];
        sm[OFF_B0 + 192 + tid] = bhh0[128 + tid];
        sm[OFF_B1 + tid]       = bih1[tid]       + bhh1[tid];
        sm[OFF_B1 + 64 + tid]  = bih1[64 + tid]  + bhh1[64 + tid];
        sm[OFF_B1 + 128 + tid] = bih1[128 + tid];
        sm[OFF_B1 + 192 + tid] = bhh1[128 + tid];
    }
}

extern "C" __global__ void __launch_bounds__(NT, 1)
gru_controller_kernel(const float* __restrict__ x,
                      const float* eWih0, const float* eWhh0, const float* ebih0, const float* ebhh0,
                      const float* eWih1, const float* eWhh1, const float* ebih1, const float* ebhh1,
                      const float* dWih0, const float* dWhh0, const float* dbih0, const float* dbhh0,
                      const float* dWih1, const float* dWhh1, const float* dbih1, const float* dbhh1,
                      const float* __restrict__ outW, const float* __restrict__ outb,
                      float* __restrict__ out) {
    extern __shared__ float sm[];
    u32* smw = (u32*)sm;
    const int tid = threadIdx.x;
    const int w = tid >> 5, l = tid & 31;
    const int mg = w >> 3, jg = w & 7;      // half mg (rows mg*32..+31), n-tile jg
    const int g = l >> 2, tq = l & 3;
    const int rb0 = mg * 32;
    const int rbase = blockIdx.x * 64;
    const int lt = tid & 255;               // thread id within half

    // half-scoped barrier (256 threads of this half)
    auto barh = [&]() {
        asm volatile("bar.sync %0, 256;" :: "r"(1 + mg) : "memory");
    };

    float aR[2][4], aZ[2][4], aI[2][4], aH[2][4];   // [mt][q]
    uint2 bl0[3][4];   // L0 B-frags [gate][ch] for n-tile jg
    uint2 bl1[3][8];   // L1 B-frags

    auto load_b_regs = [&]() {
#pragma unroll
        for (int gate = 0; gate < 3; gate++)
#pragma unroll
            for (int ch = 0; ch < 4; ch++)
                bl0[gate][ch] =
                    *(const uint2*)&smw[OFF_BL0 + (gate * 32 + jg * 4 + ch) * 64 + l * 2];
#pragma unroll
        for (int gate = 0; gate < 3; gate++)
#pragma unroll
            for (int ch = 0; ch < 8; ch++)
                bl1[gate][ch] =
                    *(const uint2*)&smw[OFF_BL1 + (gate * 64 + jg * 8 + ch) * 64 + l * 2];
    };

    auto init_gates = [&](const float* b, bool withX, int slot) {
        const int col0 = jg * 8 + 2 * tq;
        float2 bR = *(const float2*)&b[col0];
        float2 bZ = *(const float2*)&b[64 + col0];
        float2 bI = *(const float2*)&b[128 + col0];
        float2 bH = *(const float2*)&b[192 + col0];
        if (withX) {
            float2 wr0 = *(const float2*)&sm[OFF_W0S + col0 * 2];
            float2 wr1 = *(const float2*)&sm[OFF_W0S + (col0 + 1) * 2];
            float2 wz0 = *(const float2*)&sm[OFF_W0S + (64 + col0) * 2];
            float2 wz1 = *(const float2*)&sm[OFF_W0S + (64 + col0 + 1) * 2];
            float2 wn0 = *(const float2*)&sm[OFF_W0S + (128 + col0) * 2];
            float2 wn1 = *(const float2*)&sm[OFF_W0S + (128 + col0 + 1) * 2];
#pragma unroll
            for (int mt = 0; mt < 2; mt++) {
                float2 xlo = *(const float2*)&sm[OFF_XST + slot * 128 + (rb0 + mt * 16 + g) * 2];
                float2 xhi = *(const float2*)&sm[OFF_XST + slot * 128 + (rb0 + mt * 16 + g + 8) * 2];
#pragma unroll
                for (int h = 0; h < 2; h++) {
                    float x0 = h ? xhi.x : xlo.x;
                    float x1 = h ? xhi.y : xlo.y;
                    aR[mt][2 * h]     = bR.x + x0 * wr0.x + x1 * wr0.y;
                    aR[mt][2 * h + 1] = bR.y + x0 * wr1.x + x1 * wr1.y;
                    aZ[mt][2 * h]     = bZ.x + x0 * wz0.x + x1 * wz0.y;
                    aZ[mt][2 * h + 1] = bZ.y + x0 * wz1.x + x1 * wz1.y;
                    aI[mt][2 * h]     = bI.x + x0 * wn0.x + x1 * wn0.y;
                    aI[mt][2 * h + 1] = bI.y + x0 * wn1.x + x1 * wn1.y;
                    aH[mt][2 * h]     = bH.x;
                    aH[mt][2 * h + 1] = bH.y;
                }
            }
        } else {
#pragma unroll
            for (int mt = 0; mt < 2; mt++) {
                aR[mt][0] = bR.x; aR[mt][1] = bR.y; aR[mt][2] = bR.x; aR[mt][3] = bR.y;
                aZ[mt][0] = bZ.x; aZ[mt][1] = bZ.y; aZ[mt][2] = bZ.x; aZ[mt][3] = bZ.y;
                aI[mt][0] = bI.x; aI[mt][1] = bI.y; aI[mt][2] = bI.x; aI[mt][3] = bI.y;
                aH[mt][0] = bH.x; aH[mt][1] = bH.y; aH[mt][2] = bH.x; aH[mt][3] = bH.y;
            }
        }
    };

    auto mma_l0 = [&](const u32* hs) {
#pragma unroll
        for (int ch = 0; ch < 4; ch++) {
            u32 a[2][4];
#pragma unroll
            for (int mt = 0; mt < 2; mt++) {
                int rlo = rb0 + mt * 16 + g;
                uint2 lo = *(const uint2*)&hs[rlo * HSW + ch * 8 + tq * 2];
                uint2 hi = *(const uint2*)&hs[(rlo + 8) * HSW + ch * 8 + tq * 2];
                a[mt][0] = lo.x; a[mt][1] = hi.x; a[mt][2] = lo.y; a[mt][3] = hi.y;
            }
#pragma unroll
            for (int mt = 0; mt < 2; mt++) {
                mma16(aR[mt], a[mt][0], a[mt][1], a[mt][2], a[mt][3], bl0[0][ch].x, bl0[0][ch].y);
                mma16(aZ[mt], a[mt][0], a[mt][1], a[mt][2], a[mt][3], bl0[1][ch].x, bl0[1][ch].y);
                mma16(aH[mt], a[mt][0], a[mt][1], a[mt][2], a[mt][3], bl0[2][ch].x, bl0[2][ch].y);
            }
        }
    };

    auto mma_l1 = [&](const u32* h0, const u32* h1) {
#pragma unroll
        for (int ch = 0; ch < 8; ch++) {
            const u32* hs = (ch < 4) ? h0 : h1;
            int kw = (ch & 3) * 8 + tq * 2;
            u32 a[2][4];
#pragma unroll
            for (int mt = 0; mt < 2; mt++) {
                int rlo = rb0 + mt * 16 + g;
                uint2 lo = *(const uint2*)&hs[rlo * HSW + kw];
                uint2 hi = *(const uint2*)&hs[(rlo + 8) * HSW + kw];
                a[mt][0] = lo.x; a[mt][1] = hi.x; a[mt][2] = lo.y; a[mt][3] = hi.y;
            }
#pragma unroll
            for (int mt = 0; mt < 2; mt++) {
                mma16(aR[mt], a[mt][0], a[mt][1], a[mt][2], a[mt][3], bl1[0][ch].x, bl1[0][ch].y);
                mma16(aZ[mt], a[mt][0], a[mt][1], a[mt][2], a[mt][3], bl1[1][ch].x, bl1[1][ch].y);
                if (ch < 4)
                    mma16(aI[mt], a[mt][0], a[mt][1], a[mt][2], a[mt][3], bl1[2][ch].x, bl1[2][ch].y);
                else
                    mma16(aH[mt], a[mt][0], a[mt][1], a[mt][2], a[mt][3], bl1[2][ch].x, bl1[2][ch].y);
            }
        }
    };

    // fp32 epilogue (R11 arithmetic). h word for n-tile jg at 2tq:
    // pair q = 4*jg+tq -> word 8(jg>>1)+2tq+(jg&1)
    auto update = [&](const u32* hs, u32* hd, bool head) {
        const int wq = 8 * (jg >> 1) + 2 * tq + (jg & 1);
        float pr[2][2] = {{0.0f, 0.0f}, {0.0f, 0.0f}};
        float2 wo = head ? *(const float2*)&sm[OFF_OUTW + jg * 8 + 2 * tq]
                         : make_float2(0.f, 0.f);
#pragma unroll
        for (int mt = 0; mt < 2; mt++) {
            int rlo = rb0 + mt * 16 + g, rhi = rlo + 8;
            float2 hlo = unpack_h2(hs[rlo * HSW + wq]);
            float2 hhi = unpack_h2(hs[rhi * HSW + wq]);
            const float hold[4] = {hlo.x, hlo.y, hhi.x, hhi.y};
            float o[4];
#pragma unroll
            for (int q = 0; q < 4; q++) {
                float r = sigm_t(aR[mt][q]);
                float z = sigm_t(aZ[mt][q]);
                float n = tanh_t(fmaf(r, aH[mt][q], aI[mt][q]));
                o[q] = fmaf(z, hold[q] - n, n);
            }
            hd[rlo * HSW + wq] = pack_h2(o[0], o[1]);
            hd[rhi * HSW + wq] = pack_h2(o[2], o[3]);
            if (head) {
                pr[mt][0] = fmaf(o[0], wo.x, fmaf(o[1], wo.y, pr[mt][0]));
                pr[mt][1] = fmaf(o[2], wo.x, fmaf(o[3], wo.y, pr[mt][1]));
            }
        }
        if (head) {
#pragma unroll
            for (int mt = 0; mt < 2; mt++)
#pragma unroll
                for (int h = 0; h < 2; h++) {
                    float v = pr[mt][h];
                    v += __shfl_xor_sync(0xffffffffu, v, 1);
                    v += __shfl_xor_sync(0xffffffffu, v, 2);
                    if (tq == 0)
                        sm[OFF_PART + jg * 64 + rb0 + mt * 16 + h * 8 + g] = v;
                }
        }
    };

    // stage x(t) for this half's 32 rows into slot
    auto stage_x = [&](int t, int slot) {
        if (lt < 64) {
            int r = rb0 + (lt >> 1), ch = lt & 1;
            sm[OFF_XST + slot * 128 + r * 2 + ch] = x[((long)(rbase + r) * TIN + t) * 2 + ch];
        }
    };

    // ---------------- setup ----------------
    for (int i = tid; i < 4 * 64 * HSW; i += NT) smw[OFF_H0A + i] = 0u;
    load_weights_tc(sm, eWih0, 2, eWhh0, ebih0, ebhh0, eWih1, eWhh1, ebih1, ebhh1, tid);
    if (tid < 64) sm[OFF_OUTW + tid] = outW[tid];
    __syncthreads();
    load_b_regs();
    stage_x(0, 0);
    barh();

    int p = 0;
    // ================= encoder (per-half, 1 named barrier/step) =================
    for (int t = 0; t < TIN; t++) {
        const u32* h0s = smw + (p ? OFF_H0B : OFF_H0A);
        u32*       h0d = smw + (p ? OFF_H0A : OFF_H0B);
        const u32* h1s = smw + (p ? OFF_H1B : OFF_H1A);
        u32*       h1d = smw + (p ? OFF_H1A : OFF_H1B);

        if (t + 1 < TIN) stage_x(t + 1, (t + 1) & 1);

        init_gates(sm + OFF_B0, true, t & 1);
        mma_l0(h0s);
        update(h0s, h0d, false);
        barh();   // layer0-write -> layer1-read (within half)

        init_gates(sm + OFF_B1, false, 0);
        mma_l1(h0d, h1s);
        update(h1s, h1d, false);
        p ^= 1;
    }

    // ================= swap to decoder weights =================
    __syncthreads();   // both halves done with encoder weights/biases
    load_weights_tc(sm, dWih0, 1, dWhh0, dbih0, dbhh0, dWih1, dWhh1, dbih1, dbhh1, tid);
    if (tid < 64) {
        sm[OFF_XST + tid * 2]     = 0.0f;
        sm[OFF_XST + tid * 2 + 1] = 0.0f;
    }
    __syncthreads();
    load_b_regs();
    const float ob = outb[0];

    // ================= decoder (per-half) =================
    for (int t = 0; t < TOUT; t++) {
        const u32* h0s = smw + (p ? OFF_H0B : OFF_H0A);
        u32*       h0d = smw + (p ? OFF_H0A : OFF_H0B);
        const u32* h1s = smw + (p ? OFF_H1B : OFF_H1A);
        u32*       h1d = smw + (p ? OFF_H1A : OFF_H1B);

        init_gates(sm + OFF_B0, true, 0);   // prev in slot 0
        mma_l0(h0s);
        update(h0s, h0d, false);
        barh();

        init_gates(sm + OFF_B1, false, 0);
        mma_l1(h0d, h1s);
        update(h1s, h1d, true);
        barh();

        if (lt < 32) {
            int r = rb0 + lt;
            float acc = ob;
#pragma unroll
            for (int c = 0; c < 8; c++) acc += sm[OFF_PART + c * 64 + r];
            sm[OFF_XST + r * 2] = acc;     // prev for next step (channel 1 stays 0)
            out[(long)(rbase + r) * TOUT + t] = acc;
        }
        barh();
        p ^= 1;
    }
}

extern "C" void kernel_launch(void* const* d_in, const int* in_sizes, int n_in,
                              void* d_out, int out_size) {
    const float* x     = (const float*)d_in[0];
    const float* eWih0 = (const float*)d_in[1];
    const float* eWhh0 = (const float*)d_in[2];
    const float* ebih0 = (const float*)d_in[3];
    const float* ebhh0 = (const float*)d_in[4];
    const float* eWih1 = (const float*)d_in[5];
    const float* eWhh1 = (const float*)d_in[6];
    const float* ebih1 = (const float*)d_in[7];
    const float* ebhh1 = (const float*)d_in[8];
    const float* dWih0 = (const float*)d_in[9];
    const float* dWhh0 = (const float*)d_in[10];
    const float* dbih0 = (const float*)d_in[11];
    const float* dbhh0 = (const float*)d_in[12];
    const float* dWih1 = (const float*)d_in[13];
    const float* dWhh1 = (const float*)d_in[14];
    const float* dbih1 = (const float*)d_in[15];
    const float* dbhh1 = (const float*)d_in[16];
    const float* outW  = (const float*)d_in[17];
    const float* outb  = (const float*)d_in[18];
    float* out = (float*)d_out;

    cudaFuncSetAttribute(gru_controller_kernel,
                         cudaFuncAttributeMaxDynamicSharedMemorySize, SMEM_BYTES);
    gru_controller_kernel<<<128, NT, SMEM_BYTES>>>(
        x, eWih0, eWhh0, ebih0, ebhh0, eWih1, eWhh1, ebih1, ebhh1,
        dWih0, dWhh0, dbih0, dbhh0, dWih1, dWhh1, dbih1, dbhh1,
        outW, outb, out);
}